// round 16
// baseline (speedup 1.0000x reference)
#include <cuda_runtime.h>

// EPLoss edit-probability DP — warp-specialized wavefront. One CTA (96 thr)
// per batch item. B=128, n_y=512, n_T=128, C=128. EOS = 1.
//
// R16: per-column cost (~155 cyc) proved schedule-invariant across 5 rounds
// -> it is tied to the per-column work MIX on the single warp (8 conflicted
// gather LDS + staging + shfl + recurrence). Split roles:
//   warp 0 (consumer): DP recurrence only. Per column: shfl + 2x LDS.128
//     (precomputed rg/rh coefficient rows) + 1 scalar LDS + ~16 FP.
//   warp 1 (P-producer): stages pred rows via cp.async, gathers
//     rg[j][i] = R0[j-1]*pred[b,j-1,t_{i-1}], STS.128 into CBUF.
//   warp 2 (I-producer): same for rh[j][i] = Rins[j]*I[b,j,t_{i-1}].
// CBUF = 128-column ring (4 chunks of 32), stride 136 floats (bank-optimal
// 4-phase for both the consumer's skewed float4 reads and producer writes).
// Pipeline: during iter k, producers build chunk k+1 (rows staged iter k-1)
// and stage rows for chunk k+2; consumer runs steps 32k..32k+31 (touching
// column chunks k-1,k). One __syncthreads per iter (17 total).

#define NY 512
#define NT 128
#define CC 128

#define PR_SLOTS 64
#define PR_STRIDE 132        // floats; pad word [128] = 0 (lane-0 row-0 trick)
#define PR_STRIDE_B (PR_STRIDE * 4)
#define CB_SLOTS 128
#define CB_STRIDE 136        // floats; 544 B, 16B-aligned, 4-phase optimal

#define OFF_PRING 0
#define OFF_IRING (PR_SLOTS * PR_STRIDE)
#define OFF_RG    (2 * PR_SLOTS * PR_STRIDE)
#define OFF_RH    (OFF_RG + CB_SLOTS * CB_STRIDE)
#define OFF_RX    (OFF_RH + CB_SLOTS * CB_STRIDE)
#define OFF_RY    (OFF_RX + NY)
#define OFF_RZ    (OFF_RY + NY)
#define SMEM_FLOATS (OFF_RZ + NY)

__global__ __launch_bounds__(96, 1)
void ep_ws(const float* __restrict__ pred,
           const float* __restrict__ R,
           const float* __restrict__ Iins,
           const int* __restrict__ target,
           float* __restrict__ out) {
    extern __shared__ float smem[];
    float* Pring = smem + OFF_PRING;
    float* Iring = smem + OFF_IRING;
    float* RG    = smem + OFF_RG;
    float* RH    = smem + OFF_RH;
    float* Rx    = smem + OFF_RX;
    float* Ry    = smem + OFF_RY;
    float* Rz    = smem + OFF_RZ;

    const int tid  = threadIdx.x;
    const int w    = tid >> 5;
    const int lane = tid & 31;
    const int b    = blockIdx.x;

    const float* __restrict__ predb = pred + (size_t)b * NY * CC;
    const float* __restrict__ Ib    = Iins + (size_t)b * NY * CC;
    const float* __restrict__ Rb    = R    + (size_t)b * NY * 3;
    const int*   __restrict__ tb    = target + b * NT;

    const unsigned PringS = (unsigned)__cvta_generic_to_shared(Pring);
    const unsigned IringS = (unsigned)__cvta_generic_to_shared(Iring);
    const unsigned laneOff = (unsigned)(lane * 16);

    // ---- shared setup (all warps) ----
    for (int j = tid; j < NY; j += 96) {
        Rx[j] = Rb[3 * j + 0];
        Ry[j] = (j == NY - 1) ? 1.0f : Rb[3 * j + 1];
        Rz[j] = Rb[3 * j + 2];
    }
    for (int k = tid; k < PR_SLOTS * 4; k += 96) {
        const int r = k >> 2, wd = k & 3;
        Pring[r * PR_STRIDE + CC + wd] = 0.0f;
        Iring[r * PR_STRIDE + CC + wd] = 0.0f;
    }

    // Per-lane gather classes (used by producers; pad class CC for row 0).
    const int r0row = lane * 4;
    const int tg0 = lane ? tb[r0row - 1] : CC;
    const int tg1 = tb[r0row + 0];
    const int tg2 = tb[r0row + 1];
    const int tg3 = tb[r0row + 2];

    // Consumer-only state.
    const bool e0 = (tb[r0row + 0] == 1), e1 = (tb[r0row + 1] == 1);
    const bool e2 = (tb[r0row + 2] == 1), e3 = (tb[r0row + 3] == 1);
    const bool isl0 = (lane == 0);
    const float rins1 = Rb[3 * 1 + 1];
    const float pI1_0 = rins1 * Ib[CC + (lane ? tb[r0row - 1] : 0)];
    const float pI1_1 = rins1 * Ib[CC + tg1];
    const float pI1_2 = rins1 * Ib[CC + tg2];
    const float pI1_3 = rins1 * Ib[CC + tg3];

    // ---- producer staging macros (rows r0..r0+31, one commit group) ----
#define STAGE32(BASE_S, SRC_, R0_) do {                                         \
    _Pragma("unroll")                                                           \
    for (int q_ = 0; q_ < 32; ++q_) {                                           \
        const int r_ = (R0_) + q_;                                              \
        const unsigned d_ = (BASE_S) + (unsigned)((r_ & (PR_SLOTS - 1)) * PR_STRIDE_B) + laneOff; \
        const float* s_ = (SRC_) + (size_t)r_ * CC + lane * 4;                  \
        asm volatile("cp.async.cg.shared.global [%0], [%1], 16;"                \
                     :: "r"(d_), "l"(s_));                                      \
    }                                                                           \
    asm volatile("cp.async.commit_group;");                                     \
} while (0)

#define STAGE_N(BASE_S, SRC_, R0_, N_) do {                                     \
    _Pragma("unroll")                                                           \
    for (int q_ = 0; q_ < (N_); ++q_) {                                         \
        const int r_ = (R0_) + q_;                                              \
        const unsigned d_ = (BASE_S) + (unsigned)((r_ & (PR_SLOTS - 1)) * PR_STRIDE_B) + laneOff; \
        const float* s_ = (SRC_) + (size_t)r_ * CC + lane * 4;                  \
        asm volatile("cp.async.cg.shared.global [%0], [%1], 16;"                \
                     :: "r"(d_), "l"(s_));                                      \
    }                                                                           \
    asm volatile("cp.async.commit_group;");                                     \
} while (0)

    // Producer prologue staging (before first barrier):
    if (w == 1) {
        STAGE_N(PringS, predb, 0, 31);   // rows 0..30  (chunk 0: cols 1..31)
        STAGE32(PringS, predb, 31);      // rows 31..62 (chunk 1: cols 32..63)
    } else if (w == 2) {
        STAGE32(IringS, Ib, 0);          // rows 0..31
        STAGE32(IringS, Ib, 32);         // rows 32..63
    }

    __syncthreads();   // Rx/Ry/Rz + ring pads visible

    // ---- producer chunk builders ----
    // P: col c -> RG[c] = Rx[c-1] * predRow(c-1)[tg*]
#define PROD_P_COL(C_) do {                                                     \
    const int c_ = (C_);                                                        \
    const float* bas_ = Pring + ((c_ - 1) & (PR_SLOTS - 1)) * PR_STRIDE;        \
    const float rx_ = Rx[c_ - 1];                                               \
    float4 v_;                                                                  \
    v_.x = rx_ * bas_[tg0]; v_.y = rx_ * bas_[tg1];                             \
    v_.z = rx_ * bas_[tg2]; v_.w = rx_ * bas_[tg3];                             \
    *(float4*)(RG + (c_ & (CB_SLOTS - 1)) * CB_STRIDE + (lane << 2)) = v_;      \
} while (0)

    // I: col c -> RH[c] = Ry[c] * IRow(c)[tg*]
#define PROD_I_COL(C_) do {                                                     \
    const int c_ = (C_);                                                        \
    const float* bas_ = Iring + (c_ & (PR_SLOTS - 1)) * PR_STRIDE;              \
    const float ry_ = Ry[c_];                                                   \
    float4 v_;                                                                  \
    v_.x = ry_ * bas_[tg0]; v_.y = ry_ * bas_[tg1];                             \
    v_.z = ry_ * bas_[tg2]; v_.w = ry_ * bas_[tg3];                             \
    *(float4*)(RH + (c_ & (CB_SLOTS - 1)) * CB_STRIDE + (lane << 2)) = v_;      \
} while (0)

    // Producers build chunk 0 (cols 1..31).
    if (w == 1) {
        asm volatile("cp.async.wait_group 1;" ::: "memory");
#pragma unroll 4
        for (int c = 1; c < 32; ++c) PROD_P_COL(c);
    } else if (w == 2) {
        asm volatile("cp.async.wait_group 1;" ::: "memory");
#pragma unroll 4
        for (int c = 1; c < 32; ++c) PROD_I_COL(c);
    }

    __syncthreads();   // chunk 0 ready

    // ---- consumer state ----
    float cur0 = 0.f, cur1 = 0.f, cur2 = 0.f, cur3 = 0.f;
    float carry = 0.f;   // cur3 at end of previous step
    float upp   = 0.f;   // previous step's shfl = ep[r0-1, j-1]
    float rpz   = 0.f;   // R2[j-1]

    // Column body, j >= 1. Lane 0's rg.x/rh.x are 0 (pad class) ->
    // n0 = cur0 * (e0 ? 1 : Rz[j]) == row-0 cumprod.
#define C_BODY(J_, UPP_, UPC_) do {                                             \
    const int sl_ = (J_) & (CB_SLOTS - 1);                                      \
    const float4 rg_ = *(const float4*)(RG + sl_ * CB_STRIDE + (lane << 2));    \
    const float4 rh_ = *(const float4*)(RH + sl_ * CB_STRIDE + (lane << 2));    \
    const float rz_ = Rz[(J_)];                                                 \
    const float pz0_ = isl0 ? rz_ : rpz;                                        \
    const float pd0_ = e0 ? 1.0f : pz0_;                                        \
    const float pd1_ = e1 ? 1.0f : rpz;                                         \
    const float pd2_ = e2 ? 1.0f : rpz;                                         \
    const float pd3_ = e3 ? 1.0f : rpz;                                         \
    const float c0_ = fmaf((UPP_), rg_.x, cur0 * pd0_);                         \
    const float n0_ = fmaf((UPC_), rh_.x, c0_);                                 \
    const float c1_ = fmaf(cur0, rg_.y, cur1 * pd1_);                           \
    const float n1_ = fmaf(n0_, rh_.y, c1_);                                    \
    const float c2_ = fmaf(cur1, rg_.z, cur2 * pd2_);                           \
    const float n2_ = fmaf(n1_, rh_.z, c2_);                                    \
    const float c3_ = fmaf(cur2, rg_.w, cur3 * pd3_);                           \
    const float n3_ = fmaf(n2_, rh_.w, c3_);                                    \
    cur0 = n0_; cur1 = n1_; cur2 = n2_; cur3 = n3_;                             \
    rpz = rz_;                                                                  \
} while (0)

#define C_STEADY(S_) do {                                                       \
    const float upc_ = __shfl_up_sync(0xffffffffu, carry, 1);                   \
    C_BODY((S_) - lane, upp, upc_);                                             \
    upp = upc_; carry = cur3;                                                   \
} while (0)

#define C_RAMP(S_) do {                                                         \
    const float upc_ = __shfl_up_sync(0xffffffffu, carry, 1);                   \
    const int j_ = (S_) - lane;                                                 \
    if (j_ >= 0) {                                                              \
        if (j_ == 0) {                                                          \
            cur0 = lane ? (upc_ * pI1_0) : 1.0f;                                \
            cur1 = cur0 * pI1_1;                                                \
            cur2 = cur1 * pI1_2;                                                \
            cur3 = cur2 * pI1_3;                                                \
            rpz = Rz[0];                                                        \
        } else {                                                                \
            C_BODY(j_, upp, upc_);                                              \
        }                                                                       \
    }                                                                           \
    upp = upc_; carry = cur3;                                                   \
} while (0)

#define C_EPI(S_) do {                                                          \
    const float upc_ = __shfl_up_sync(0xffffffffu, carry, 1);                   \
    const int j_ = (S_) - lane;                                                 \
    if (j_ < NY) { C_BODY(j_, upp, upc_); }                                     \
    upp = upc_; carry = cur3;                                                   \
} while (0)

    // ---- main loop: 17 iters of 32 steps ----
    for (int k = 0; k < 17; ++k) {
        if (w == 0) {
            const int sb = 32 * k;
            if (k == 0) {
#pragma unroll 8
                for (int u = 0; u < 32; ++u) C_RAMP(u);
            } else if (k < 16) {
#pragma unroll 8
                for (int u = 0; u < 32; ++u) C_STEADY(sb + u);
            } else {
                for (int u = 0; u < 32; ++u) C_EPI(sb + u);
            }
        } else if (w == 1) {
            const bool staged = (k + 2 <= 15);
            if (staged) STAGE32(PringS, predb, 32 * (k + 2) - 1);
            if (k + 1 <= 15) {
                if (staged) { asm volatile("cp.async.wait_group 1;" ::: "memory"); }
                else        { asm volatile("cp.async.wait_group 0;" ::: "memory"); }
                const int c0 = 32 * (k + 1);
#pragma unroll 4
                for (int q = 0; q < 32; ++q) PROD_P_COL(c0 + q);
            }
        } else {
            const bool staged = (k + 2 <= 15);
            if (staged) STAGE32(IringS, Ib, 32 * (k + 2));
            if (k + 1 <= 15) {
                if (staged) { asm volatile("cp.async.wait_group 1;" ::: "memory"); }
                else        { asm volatile("cp.async.wait_group 0;" ::: "memory"); }
                const int c0 = 32 * (k + 1);
#pragma unroll 4
                for (int q = 0; q < 32; ++q) PROD_I_COL(c0 + q);
            }
        }
        __syncthreads();
    }

    // ep[127, 511]: consumer lane 31's cur3 (last column 511 done at step 542).
    if (tid == 31) out[b] = cur3;
}

static const int kSmemBytes = SMEM_FLOATS * 4;   // 212,992 B

extern "C" void kernel_launch(void* const* d_in, const int* in_sizes, int n_in,
                              void* d_out, int out_size) {
    const float* pred   = (const float*)d_in[0];
    const float* R      = (const float*)d_in[1];
    const float* Iins   = (const float*)d_in[2];
    const int*   target = (const int*)d_in[3];
    float* out = (float*)d_out;

    cudaFuncSetAttribute(ep_ws,
                         cudaFuncAttributeMaxDynamicSharedMemorySize, kSmemBytes);

    const int B = out_size;  // 128
    ep_ws<<<B, 96, kSmemBytes>>>(pred, R, Iins, target, out);
}